// round 1
// baseline (speedup 1.0000x reference)
#include <cuda_runtime.h>
#include <cstdint>

// ---------------------------------------------------------------------------
// Problem constants (from reference)
// ---------------------------------------------------------------------------
#define B_   32
#define LQ_  300
#define D_   256
#define H_   8
#define L_   3
#define P_   4
#define HD_  32
#define LV_  8400   // 80*80 + 40*40 + 20*20

__device__ __constant__ int c_Hs[3]     = {80, 40, 20};
__device__ __constant__ int c_Ws[3]     = {80, 40, 20};
__device__ __constant__ int c_start[3]  = {0, 6400, 8000};

// ---------------------------------------------------------------------------
// Scratch (device globals -- no allocation allowed)
// ---------------------------------------------------------------------------
__device__ float g_vproj[(size_t)B_ * LV_ * D_];           // 275 MB
__device__ float g_off  [(size_t)B_ * LQ_ * H_ * L_ * P_ * 2];  // [9600,192]
__device__ float g_attn [(size_t)B_ * LQ_ * H_ * L_ * P_];      // [9600,96]
__device__ float g_samp [(size_t)B_ * LQ_ * D_];               // [9600,256]

// ---------------------------------------------------------------------------
// Generic tiled GEMM:  C[M,N] = A[M,K] @ W[K,N] + bias[N]
// 64x64 block tile, BK=16, 256 threads, 4x4 per-thread micro-tile.
// ---------------------------------------------------------------------------
#define BM 64
#define BN 64
#define BK 16

__global__ __launch_bounds__(256)
void gemm_bias_kernel(const float* __restrict__ A, const float* __restrict__ W,
                      const float* __restrict__ bias, float* __restrict__ C,
                      int M, int N, int K)
{
    __shared__ float As[BK][BM + 1];
    __shared__ float Bs[BK][BN];

    const int tid = threadIdx.x;
    const int m0  = blockIdx.y * BM;
    const int n0  = blockIdx.x * BN;
    const int ty  = tid >> 4;   // 0..15
    const int tx  = tid & 15;   // 0..15

    float acc[4][4];
#pragma unroll
    for (int i = 0; i < 4; i++)
#pragma unroll
        for (int j = 0; j < 4; j++) acc[i][j] = 0.f;

    for (int k0 = 0; k0 < K; k0 += BK) {
        // load A tile 64x16 (transposed into As[k][m])
#pragma unroll
        for (int t = 0; t < 4; t++) {
            int idx = tid + t * 256;
            int m = idx >> 4;       // /16
            int k = idx & 15;
            int gm = m0 + m;
            As[k][m] = (gm < M) ? A[(size_t)gm * K + (k0 + k)] : 0.f;
        }
        // load B tile 16x64
#pragma unroll
        for (int t = 0; t < 4; t++) {
            int idx = tid + t * 256;
            int k = idx >> 6;       // /64
            int n = idx & 63;
            int gn = n0 + n;
            Bs[k][n] = (gn < N) ? W[(size_t)(k0 + k) * N + gn] : 0.f;
        }
        __syncthreads();

#pragma unroll
        for (int k = 0; k < BK; k++) {
            float a[4], b[4];
#pragma unroll
            for (int i = 0; i < 4; i++) a[i] = As[k][ty + i * 16];
#pragma unroll
            for (int j = 0; j < 4; j++) b[j] = Bs[k][tx + j * 16];
#pragma unroll
            for (int i = 0; i < 4; i++)
#pragma unroll
                for (int j = 0; j < 4; j++)
                    acc[i][j] += a[i] * b[j];
        }
        __syncthreads();
    }

#pragma unroll
    for (int i = 0; i < 4; i++) {
        int gm = m0 + ty + i * 16;
        if (gm >= M) continue;
#pragma unroll
        for (int j = 0; j < 4; j++) {
            int gn = n0 + tx + j * 16;
            if (gn < N)
                C[(size_t)gm * N + gn] = acc[i][j] + bias[gn];
        }
    }
}

// ---------------------------------------------------------------------------
// Sampling kernel: one warp per (b, q, h). Lane = head channel (HD_=32).
// softmax over 12 logits + 12-point bilinear gather of projected value.
// ---------------------------------------------------------------------------
__global__ __launch_bounds__(256)
void sample_kernel(const float* __restrict__ rp,
                   const float* __restrict__ off,
                   const float* __restrict__ alog,
                   const float* __restrict__ vproj,
                   float* __restrict__ out)
{
    const int gw   = (blockIdx.x * blockDim.x + threadIdx.x) >> 5;  // (b*LQ+q)*H + h
    const int lane = threadIdx.x & 31;
    if (gw >= B_ * LQ_ * H_) return;

    const int h  = gw % H_;
    const int bq = gw / H_;
    const int b  = bq / LQ_;

    // ---- softmax over the 12 attention logits (lane-redundant, broadcast) ----
    const float* al = alog + (size_t)gw * (L_ * P_);
    float w[L_ * P_];
    float mx = -1e30f;
#pragma unroll
    for (int i = 0; i < L_ * P_; i++) { w[i] = al[i]; mx = fmaxf(mx, w[i]); }
    float s = 0.f;
#pragma unroll
    for (int i = 0; i < L_ * P_; i++) { w[i] = __expf(w[i] - mx); s += w[i]; }
    const float inv = 1.f / s;

    const float* offp = off + (size_t)gw * (L_ * P_ * 2);
    const float* rpp  = rp + (size_t)bq * (L_ * 4);
    // vproj base for this batch/head/channel
    const float* vb = vproj + ((size_t)b * LV_) * D_ + h * HD_ + lane;

    float acc = 0.f;

#pragma unroll
    for (int l = 0; l < L_; l++) {
        const float cx = rpp[l * 4 + 0];
        const float cy = rpp[l * 4 + 1];
        const float hw = rpp[l * 4 + 2] * 0.5f;
        const float hh = rpp[l * 4 + 3] * 0.5f;
        const int Wl = c_Ws[l], Hl = c_Hs[l], s0 = c_start[l];
        const float* base = vb + (size_t)s0 * D_;

#pragma unroll
        for (int p = 0; p < P_; p++) {
            const float lx = cx + offp[(l * P_ + p) * 2 + 0] * hw;
            const float ly = cy + offp[(l * P_ + p) * 2 + 1] * hh;
            const float x = lx * (float)Wl - 0.5f;
            const float y = ly * (float)Hl - 0.5f;
            const float x0f = floorf(x), y0f = floorf(y);
            const int   x0 = (int)x0f,  y0 = (int)y0f;
            const float wx1 = x - x0f, wx0 = 1.f - wx1;
            const float wy1 = y - y0f, wy0 = 1.f - wy1;
            const float aw = w[l * P_ + p] * inv;

            const bool xv0 = (x0 >= 0)     && (x0 < Wl);
            const bool xv1 = (x0 + 1 >= 0) && (x0 + 1 < Wl);
            const bool yv0 = (y0 >= 0)     && (y0 < Hl);
            const bool yv1 = (y0 + 1 >= 0) && (y0 + 1 < Hl);

            float v00 = 0.f, v10 = 0.f, v01 = 0.f, v11 = 0.f;
            if (yv0) {
                const size_t ro = (size_t)(y0 * Wl);
                if (xv0) v00 = base[(ro + x0) * D_];
                if (xv1) v10 = base[(ro + x0 + 1) * D_];
            }
            if (yv1) {
                const size_t ro = (size_t)((y0 + 1) * Wl);
                if (xv0) v01 = base[(ro + x0) * D_];
                if (xv1) v11 = base[(ro + x0 + 1) * D_];
            }
            acc += aw * (wy0 * (wx0 * v00 + wx1 * v10) +
                         wy1 * (wx0 * v01 + wx1 * v11));
        }
    }

    out[(size_t)gw * HD_ + lane] = acc;
}

// ---------------------------------------------------------------------------
// Launch
// ---------------------------------------------------------------------------
extern "C" void kernel_launch(void* const* d_in, const int* in_sizes, int n_in,
                              void* d_out, int out_size)
{
    const float* query = (const float*)d_in[0];
    const float* rp    = (const float*)d_in[1];
    const float* value = (const float*)d_in[2];
    // d_in[3] spatial_shapes (int32), d_in[4] level_start_index (int32) -- constants, hardcoded
    const float* Wv    = (const float*)d_in[5];
    const float* bv    = (const float*)d_in[6];
    const float* Woff  = (const float*)d_in[7];
    const float* boff  = (const float*)d_in[8];
    const float* Wattn = (const float*)d_in[9];
    const float* battn = (const float*)d_in[10];
    const float* Wout  = (const float*)d_in[11];
    const float* bout  = (const float*)d_in[12];
    float* out = (float*)d_out;

    float *vproj, *offb, *attnb, *samp;
    cudaGetSymbolAddress((void**)&vproj, g_vproj);
    cudaGetSymbolAddress((void**)&offb,  g_off);
    cudaGetSymbolAddress((void**)&attnb, g_attn);
    cudaGetSymbolAddress((void**)&samp,  g_samp);

    const int Mv = B_ * LV_;     // 268800
    const int Mq = B_ * LQ_;     // 9600

    // 1) value projection: [Mv,256] @ [256,256] + bv
    {
        dim3 grid((D_ + BN - 1) / BN, (Mv + BM - 1) / BM);
        gemm_bias_kernel<<<grid, 256>>>(value, Wv, bv, vproj, Mv, D_, D_);
    }
    // 2) offsets: [Mq,256] @ [256,192] + boff
    {
        const int N = H_ * L_ * P_ * 2;  // 192
        dim3 grid((N + BN - 1) / BN, (Mq + BM - 1) / BM);
        gemm_bias_kernel<<<grid, 256>>>(query, Woff, boff, offb, Mq, N, D_);
    }
    // 3) attention logits: [Mq,256] @ [256,96] + battn
    {
        const int N = H_ * L_ * P_;      // 96
        dim3 grid((N + BN - 1) / BN, (Mq + BM - 1) / BM);
        gemm_bias_kernel<<<grid, 256>>>(query, Wattn, battn, attnb, Mq, N, D_);
    }
    // 4) softmax + bilinear sampling -> samp [Mq, 256]
    {
        const int warps = B_ * LQ_ * H_;            // 76800
        const int blocks = (warps * 32 + 255) / 256; // 9600
        sample_kernel<<<blocks, 256>>>(rp, offb, attnb, vproj, samp);
    }
    // 5) output projection: [Mq,256] @ [256,256] + bout -> d_out
    {
        dim3 grid((D_ + BN - 1) / BN, (Mq + BM - 1) / BM);
        gemm_bias_kernel<<<grid, 256>>>(samp, Wout, bout, out, Mq, D_, D_);
    }
}

// round 2
// speedup vs baseline: 3.4940x; 3.4940x over previous
#include <cuda_runtime.h>
#include <cstdint>

// ---------------------------------------------------------------------------
// Problem constants (from reference)
// ---------------------------------------------------------------------------
#define B_   32
#define LQ_  300
#define D_   256
#define H_   8
#define L_   3
#define P_   4
#define HD_  32
#define LV_  8400   // 80*80 + 40*40 + 20*20

// ---------------------------------------------------------------------------
// Scratch (device globals -- no allocation allowed)
// ---------------------------------------------------------------------------
__device__ float g_off  [(size_t)B_ * LQ_ * H_ * L_ * P_ * 2];  // [9600,192]
__device__ float g_attn [(size_t)B_ * LQ_ * H_ * L_ * P_];      // [9600,96]
__device__ float g_samp [(size_t)B_ * LQ_ * D_];                // [9600,256]

// ---------------------------------------------------------------------------
// Generic tiled GEMM:  C[M,N] = A[M,K] @ W[K,N] + bias[N]
// 64x64 block tile, BK=16, 256 threads, 4x4 per-thread micro-tile.
// ---------------------------------------------------------------------------
#define BM 64
#define BN 64
#define BK 16

__global__ __launch_bounds__(256)
void gemm_bias_kernel(const float* __restrict__ A, const float* __restrict__ W,
                      const float* __restrict__ bias, float* __restrict__ C,
                      int M, int N, int K)
{
    __shared__ float As[BK][BM + 1];
    __shared__ float Bs[BK][BN];

    const int tid = threadIdx.x;
    const int m0  = blockIdx.y * BM;
    const int n0  = blockIdx.x * BN;
    const int ty  = tid >> 4;   // 0..15
    const int tx  = tid & 15;   // 0..15

    float acc[4][4];
#pragma unroll
    for (int i = 0; i < 4; i++)
#pragma unroll
        for (int j = 0; j < 4; j++) acc[i][j] = 0.f;

    for (int k0 = 0; k0 < K; k0 += BK) {
#pragma unroll
        for (int t = 0; t < 4; t++) {
            int idx = tid + t * 256;
            int m = idx >> 4;
            int k = idx & 15;
            int gm = m0 + m;
            As[k][m] = (gm < M) ? A[(size_t)gm * K + (k0 + k)] : 0.f;
        }
#pragma unroll
        for (int t = 0; t < 4; t++) {
            int idx = tid + t * 256;
            int k = idx >> 6;
            int n = idx & 63;
            int gn = n0 + n;
            Bs[k][n] = (gn < N) ? W[(size_t)(k0 + k) * N + gn] : 0.f;
        }
        __syncthreads();

#pragma unroll
        for (int k = 0; k < BK; k++) {
            float a[4], b[4];
#pragma unroll
            for (int i = 0; i < 4; i++) a[i] = As[k][ty + i * 16];
#pragma unroll
            for (int j = 0; j < 4; j++) b[j] = Bs[k][tx + j * 16];
#pragma unroll
            for (int i = 0; i < 4; i++)
#pragma unroll
                for (int j = 0; j < 4; j++)
                    acc[i][j] += a[i] * b[j];
        }
        __syncthreads();
    }

#pragma unroll
    for (int i = 0; i < 4; i++) {
        int gm = m0 + ty + i * 16;
        if (gm >= M) continue;
#pragma unroll
        for (int j = 0; j < 4; j++) {
            int gn = n0 + tx + j * 16;
            if (gn < N)
                C[(size_t)gm * N + gn] = acc[i][j] + bias[gn];
        }
    }
}

// ---------------------------------------------------------------------------
// Fused sampling + per-head value projection.
//
// Linearity trick: bilinear-sample the RAW value (all 256 channels), then
// project the accumulated sample with Wv's per-head column block:
//   sampled_h = raw @ Wv[:, h*32:(h+1)*32] + wsum * bv[h*32:(h+1)*32]
// where raw = sum_{l,p,corners} cw * value[b, idx, :] and
//       wsum = sum of all (valid) corner weights * attention weights.
//
// Block: 256 threads = 8 warps; warp <-> one (b,q); blockIdx.x = head.
// Grid ordered head-major so concurrent CTAs share a small set of batches
// (L2-resident value working set).
// ---------------------------------------------------------------------------
#define QW 8   // queries (warps) per block

__global__ __launch_bounds__(256)
void sample_fused_kernel(const float* __restrict__ rp,
                         const float* __restrict__ off,
                         const float* __restrict__ alog,
                         const float* __restrict__ value,  // [B, LV, 256] raw
                         const float* __restrict__ Wv,     // [256, 256]
                         const float* __restrict__ bv,     // [256]
                         float* __restrict__ samp)         // [9600, 256]
{
    __shared__ float sWv[256][32];   // Wv[:, h*32 .. h*32+31]  (32 KB)
    __shared__ float sraw[QW][256];  // staged raw samples      (8 KB)

    const int h    = blockIdx.x;
    const int tid  = threadIdx.x;
    const int warp = tid >> 5;
    const int lane = tid & 31;

    // Load this head's Wv column block into smem (coalesced 128B per row).
    {
        const float* wvh = Wv + h * HD_;
#pragma unroll
        for (int t = 0; t < 32; t++) {
            int i = tid + t * 256;          // i in [0, 8192)
            int c = i >> 5, j = i & 31;
            sWv[c][j] = wvh[(size_t)c * D_ + j];
        }
    }

    const int bq = blockIdx.y * QW + warp;  // [0, 9600)
    const int b  = bq / LQ_;
    const int gw = bq * H_ + h;

    // ---- softmax over the 12 attention logits (lane-redundant) ----
    const float* al = alog + (size_t)gw * (L_ * P_);
    float w[L_ * P_];
    float mx = -1e30f;
#pragma unroll
    for (int i = 0; i < L_ * P_; i++) { w[i] = al[i]; mx = fmaxf(mx, w[i]); }
    float ssum = 0.f;
#pragma unroll
    for (int i = 0; i < L_ * P_; i++) { w[i] = __expf(w[i] - mx); ssum += w[i]; }
    const float inv = 1.f / ssum;

    const float* offp = off + (size_t)gw * (L_ * P_ * 2);
    const float* rpp  = rp  + (size_t)bq * (L_ * 4);
    const float4* vb  = (const float4*)(value + (size_t)b * LV_ * D_);

    // raw accumulators: lane owns channels [4*lane,4*lane+4) and +128
    float4 a0 = make_float4(0.f, 0.f, 0.f, 0.f);
    float4 a1 = make_float4(0.f, 0.f, 0.f, 0.f);
    float wsum = 0.f;

    const int HsA[3] = {80, 40, 20};
    const int stA[3] = {0, 6400, 8000};

#pragma unroll
    for (int l = 0; l < L_; l++) {
        const float cx = rpp[l * 4 + 0];
        const float cy = rpp[l * 4 + 1];
        const float hw = rpp[l * 4 + 2] * 0.5f;
        const float hh = rpp[l * 4 + 3] * 0.5f;
        const int Wl = HsA[l], Hl = HsA[l], s0 = stA[l];

#pragma unroll
        for (int p = 0; p < P_; p++) {
            const float lx = cx + offp[(l * P_ + p) * 2 + 0] * hw;
            const float ly = cy + offp[(l * P_ + p) * 2 + 1] * hh;
            const float x = lx * (float)Wl - 0.5f;
            const float y = ly * (float)Hl - 0.5f;
            const float x0f = floorf(x), y0f = floorf(y);
            const int   x0 = (int)x0f,  y0 = (int)y0f;
            const float wx1 = x - x0f, wx0 = 1.f - wx1;
            const float wy1 = y - y0f, wy0 = 1.f - wy1;
            const float aw = w[l * P_ + p] * inv;

            const float fx0 = (x0 >= 0 && x0 < Wl)         ? 1.f : 0.f;
            const float fx1 = (x0 + 1 >= 0 && x0 + 1 < Wl) ? 1.f : 0.f;
            const float fy0 = (y0 >= 0 && y0 < Hl)         ? 1.f : 0.f;
            const float fy1 = (y0 + 1 >= 0 && y0 + 1 < Hl) ? 1.f : 0.f;

            const int xc0 = min(max(x0, 0), Wl - 1);
            const int xc1 = min(max(x0 + 1, 0), Wl - 1);
            const int yc0 = min(max(y0, 0), Hl - 1);
            const int yc1 = min(max(y0 + 1, 0), Hl - 1);

            const float cw00 = aw * wy0 * wx0 * fy0 * fx0;
            const float cw10 = aw * wy0 * wx1 * fy0 * fx1;
            const float cw01 = aw * wy1 * wx0 * fy1 * fx0;
            const float cw11 = aw * wy1 * wx1 * fy1 * fx1;
            wsum += cw00 + cw10 + cw01 + cw11;

            const size_t i00 = (size_t)(s0 + yc0 * Wl + xc0) * 64;  // float4 units
            const size_t i10 = (size_t)(s0 + yc0 * Wl + xc1) * 64;
            const size_t i01 = (size_t)(s0 + yc1 * Wl + xc0) * 64;
            const size_t i11 = (size_t)(s0 + yc1 * Wl + xc1) * 64;

            // corner rows: 2 fully-coalesced float4 loads per corner
            float4 r;
            r = vb[i00 + lane];
            a0.x += cw00 * r.x; a0.y += cw00 * r.y; a0.z += cw00 * r.z; a0.w += cw00 * r.w;
            r = vb[i00 + lane + 32];
            a1.x += cw00 * r.x; a1.y += cw00 * r.y; a1.z += cw00 * r.z; a1.w += cw00 * r.w;

            r = vb[i10 + lane];
            a0.x += cw10 * r.x; a0.y += cw10 * r.y; a0.z += cw10 * r.z; a0.w += cw10 * r.w;
            r = vb[i10 + lane + 32];
            a1.x += cw10 * r.x; a1.y += cw10 * r.y; a1.z += cw10 * r.z; a1.w += cw10 * r.w;

            r = vb[i01 + lane];
            a0.x += cw01 * r.x; a0.y += cw01 * r.y; a0.z += cw01 * r.z; a0.w += cw01 * r.w;
            r = vb[i01 + lane + 32];
            a1.x += cw01 * r.x; a1.y += cw01 * r.y; a1.z += cw01 * r.z; a1.w += cw01 * r.w;

            r = vb[i11 + lane];
            a0.x += cw11 * r.x; a0.y += cw11 * r.y; a0.z += cw11 * r.z; a0.w += cw11 * r.w;
            r = vb[i11 + lane + 32];
            a1.x += cw11 * r.x; a1.y += cw11 * r.y; a1.z += cw11 * r.z; a1.w += cw11 * r.w;
        }
    }

    // stage raw sample to smem (128B STS.128 per quarter-warp, conflict-free)
    ((float4*)sraw[warp])[lane]      = a0;
    ((float4*)sraw[warp])[lane + 32] = a1;

    __syncthreads();   // sWv ready + sraw visible within warp

    // per-head projection: out[j] = sum_c raw[c] * Wv[c, h*32+j]
    float o = 0.f;
    const float* rw = sraw[warp];
#pragma unroll 16
    for (int c = 0; c < 256; c++)
        o += rw[c] * sWv[c][lane];

    o += wsum * bv[h * HD_ + lane];
    samp[(size_t)bq * D_ + h * HD_ + lane] = o;
}

// ---------------------------------------------------------------------------
// Launch
// ---------------------------------------------------------------------------
extern "C" void kernel_launch(void* const* d_in, const int* in_sizes, int n_in,
                              void* d_out, int out_size)
{
    const float* query = (const float*)d_in[0];
    const float* rp    = (const float*)d_in[1];
    const float* value = (const float*)d_in[2];
    // d_in[3] spatial_shapes, d_in[4] level_start_index -- constants, hardcoded
    const float* Wv    = (const float*)d_in[5];
    const float* bv    = (const float*)d_in[6];
    const float* Woff  = (const float*)d_in[7];
    const float* boff  = (const float*)d_in[8];
    const float* Wattn = (const float*)d_in[9];
    const float* battn = (const float*)d_in[10];
    const float* Wout  = (const float*)d_in[11];
    const float* bout  = (const float*)d_in[12];
    float* out = (float*)d_out;

    float *offb, *attnb, *samp;
    cudaGetSymbolAddress((void**)&offb,  g_off);
    cudaGetSymbolAddress((void**)&attnb, g_attn);
    cudaGetSymbolAddress((void**)&samp,  g_samp);

    const int Mq = B_ * LQ_;     // 9600

    // 1) offsets: [Mq,256] @ [256,192] + boff
    {
        const int N = H_ * L_ * P_ * 2;  // 192
        dim3 grid((N + BN - 1) / BN, (Mq + BM - 1) / BM);
        gemm_bias_kernel<<<grid, 256>>>(query, Woff, boff, offb, Mq, N, D_);
    }
    // 2) attention logits: [Mq,256] @ [256,96] + battn
    {
        const int N = H_ * L_ * P_;      // 96
        dim3 grid((N + BN - 1) / BN, (Mq + BM - 1) / BM);
        gemm_bias_kernel<<<grid, 256>>>(query, Wattn, battn, attnb, Mq, N, D_);
    }
    // 3) fused softmax + raw-value bilinear sampling + per-head projection
    {
        dim3 grid(H_, Mq / QW);   // (8, 1200); head-major for L2 locality
        sample_fused_kernel<<<grid, 256>>>(rp, offb, attnb, value, Wv, bv, samp);
    }
    // 4) output projection: [Mq,256] @ [256,256] + bout -> d_out
    {
        dim3 grid((D_ + BN - 1) / BN, (Mq + BM - 1) / BM);
        gemm_bias_kernel<<<grid, 256>>>(samp, Wout, bout, out, Mq, D_, D_);
    }
}